// round 6
// baseline (speedup 1.0000x reference)
#include <cuda_runtime.h>
#include <math.h>
#include <stdint.h>

#define B_    128
#define SEQ_  200
#define VOCAB_ 1400
#define D_    256
#define H_    256
#define NCLS_ 128
#define G4H   1024

// ---------------- scratch (static __device__, no allocations) ----------------
__device__ float g_embedded[B_ * SEQ_ * D_];
__device__ float g_ux1[B_ * SEQ_ * G4H];
__device__ float g_ux2[B_ * SEQ_ * G4H];
__device__ float g_out1[B_ * SEQ_ * H_];
__device__ float g_out2[B_ * SEQ_ * H_];
__device__ float g_beta[B_ * SEQ_ * H_];
__device__ float g_alpha[B_ * SEQ_];
__device__ float g_ctx[B_ * D_];

// ---------------- packed fp32 helpers (sm_103a f32x2 pipe) ----------------
__device__ __forceinline__ void fma2(unsigned long long& d, unsigned long long a, unsigned long long b) {
    asm("fma.rn.f32x2 %0, %1, %2, %0;" : "+l"(d) : "l"(a), "l"(b));
}
__device__ __forceinline__ unsigned long long dup2(float v) {
    unsigned long long r;
    asm("mov.b64 %0, {%1, %1};" : "=l"(r) : "f"(v));
    return r;
}
__device__ __forceinline__ float2 unpack2(unsigned long long v) {
    float2 f;
    asm("mov.b64 {%0, %1}, %2;" : "=f"(f.x), "=f"(f.y) : "l"(v));
    return f;
}

// ---------------- generic fp32 tiled GEMM (f32x2 inner loop) — R3 proven ----------------
#define GBM 128
#define GBN 64
#define GBK 16

template <bool BT>
__global__ void gemm_kernel(const float* __restrict__ A, const float* __restrict__ Bm,
                            float* __restrict__ C, int M, int N, int K,
                            const float* __restrict__ bias0, const float* __restrict__ bias1)
{
    __shared__ float As[GBK][GBM + 4];
    __shared__ float Bs[GBK][GBN + 4];

    const int tid   = threadIdx.x;       // 256 threads
    const int m_blk = blockIdx.y * GBM;
    const int n_blk = blockIdx.x * GBN;
    const int tx = tid & 15;
    const int ty = tid >> 4;
    const int m0 = ty * 8;
    const int n0 = tx * 4;

    unsigned long long acc2[4][4];
#pragma unroll
    for (int i = 0; i < 4; i++)
#pragma unroll
        for (int j = 0; j < 4; j++) acc2[i][j] = 0ULL;

    const int a_row = tid >> 2;
    const int a_c4  = (tid & 3) * 4;

    for (int k0 = 0; k0 < K; k0 += GBK) {
#pragma unroll
        for (int r = 0; r < 2; r++) {
            int m = a_row + r * 64;
            float4 v = make_float4(0.f, 0.f, 0.f, 0.f);
            if (k0 + a_c4 < K)
                v = *reinterpret_cast<const float4*>(A + (size_t)(m_blk + m) * K + k0 + a_c4);
            As[a_c4 + 0][m] = v.x;
            As[a_c4 + 1][m] = v.y;
            As[a_c4 + 2][m] = v.z;
            As[a_c4 + 3][m] = v.w;
        }
        if (BT) {
            int n  = tid >> 2;
            int c4 = (tid & 3) * 4;
            float4 v = make_float4(0.f, 0.f, 0.f, 0.f);
            if (k0 + c4 < K)
                v = *reinterpret_cast<const float4*>(Bm + (size_t)(n_blk + n) * K + k0 + c4);
            Bs[c4 + 0][n] = v.x;
            Bs[c4 + 1][n] = v.y;
            Bs[c4 + 2][n] = v.z;
            Bs[c4 + 3][n] = v.w;
        } else {
            int kk = tid >> 4;
            int nn = (tid & 15) * 4;
            float4 v = make_float4(0.f, 0.f, 0.f, 0.f);
            if (k0 + kk < K)
                v = *reinterpret_cast<const float4*>(Bm + (size_t)(k0 + kk) * N + n_blk + nn);
            *reinterpret_cast<float4*>(&Bs[kk][nn]) = v;
        }
        __syncthreads();

#pragma unroll
        for (int kk = 0; kk < GBK; kk++) {
            const ulonglong2* ap = reinterpret_cast<const ulonglong2*>(&As[kk][m0]);
            ulonglong2 aA = ap[0];
            ulonglong2 aB = ap[1];
            float4 b4 = *reinterpret_cast<const float4*>(&Bs[kk][n0]);
            unsigned long long bd[4] = {dup2(b4.x), dup2(b4.y), dup2(b4.z), dup2(b4.w)};
            unsigned long long P[4] = {aA.x, aA.y, aB.x, aB.y};
#pragma unroll
            for (int p = 0; p < 4; p++)
#pragma unroll
                for (int j = 0; j < 4; j++) fma2(acc2[p][j], P[p], bd[j]);
        }
        __syncthreads();
    }

    float bv[4] = {0.f, 0.f, 0.f, 0.f};
    if (bias0) {
#pragma unroll
        for (int j = 0; j < 4; j++) bv[j] += bias0[n_blk + n0 + j];
    }
    if (bias1) {
#pragma unroll
        for (int j = 0; j < 4; j++) bv[j] += bias1[n_blk + n0 + j];
    }
#pragma unroll
    for (int p = 0; p < 4; p++) {
        float2 r0 = unpack2(acc2[p][0]);
        float2 r1 = unpack2(acc2[p][1]);
        float2 r2 = unpack2(acc2[p][2]);
        float2 r3 = unpack2(acc2[p][3]);
        float4 oA = make_float4(r0.x + bv[0], r1.x + bv[1], r2.x + bv[2], r3.x + bv[3]);
        float4 oB = make_float4(r0.y + bv[0], r1.y + bv[1], r2.y + bv[2], r3.y + bv[3]);
        *reinterpret_cast<float4*>(C + (size_t)(m_blk + m0 + 2 * p) * N + n_blk + n0)     = oA;
        *reinterpret_cast<float4*>(C + (size_t)(m_blk + m0 + 2 * p + 1) * N + n_blk + n0) = oB;
    }
}

// ---------------- persistent LSTM scan — CGA cluster of 8, DSMEM exchange ----------------
// grid = 128 CTAs = 16 clusters x 8. Cluster = (lstm, btile); rank = jtile.
// h/c live in smem permanently; slices exchanged via st.shared::cluster.
#define WJT 32
#define HS_STRIDE 260
#define SCAN_SMEM ((5 * WJT * 256 + 2 * 16 * HS_STRIDE) * 4)

__device__ __forceinline__ uint32_t smem_u32(const void* p) {
    uint32_t a;
    asm("{ .reg .u64 t; cvta.to.shared.u64 t, %1; cvt.u32.u64 %0, t; }" : "=r"(a) : "l"(p));
    return a;
}
__device__ __forceinline__ uint32_t mapa_u32(uint32_t local, uint32_t rank) {
    uint32_t r;
    asm("mapa.shared::cluster.u32 %0, %1, %2;" : "=r"(r) : "r"(local), "r"(rank));
    return r;
}
__device__ __forceinline__ void st_cluster_v2(uint32_t addr, float a, float b) {
    asm volatile("st.shared::cluster.v2.f32 [%0], {%1, %2};" :: "r"(addr), "f"(a), "f"(b) : "memory");
}
#define CLUSTER_ARRIVE() asm volatile("barrier.cluster.arrive.aligned;" ::: "memory")
#define CLUSTER_WAIT()   asm volatile("barrier.cluster.wait.aligned;" ::: "memory")

__global__ __cluster_dims__(8, 1, 1) __launch_bounds__(256) void lstm_scan_kernel(
    const float* __restrict__ Wall1, const float* __restrict__ Wd1, const float* __restrict__ Wdb1,
    const float* __restrict__ Wall2, const float* __restrict__ Wd2, const float* __restrict__ Wdb2,
    const float* __restrict__ tsp,
    const float* __restrict__ h01, const float* __restrict__ c01,
    const float* __restrict__ h02, const float* __restrict__ c02)
{
    extern __shared__ float sm[];
    float* wsm = sm;                           // [5][32][256]
    float* hsm = sm + 5 * WJT * 256;           // [16][260]
    float* csm = hsm + 16 * HS_STRIDE;         // [16][260]

    const int bid   = blockIdx.x;
    const int lstm  = bid >> 6;
    const int btile = (bid >> 3) & 7;
    const int jt    = bid & 7;                 // == cluster rank
    const int b0 = btile * 16;
    const int j0 = jt * WJT;

    const float* Wall = lstm ? Wall2 : Wall1;
    const float* Wd   = lstm ? Wd2   : Wd1;
    const float* Wdb  = lstm ? Wdb2  : Wdb1;
    const float* ux   = lstm ? g_ux2 : g_ux1;
    const float* h0   = lstm ? h02 : h01;
    const float* c0   = lstm ? c02 : c01;
    float*       outp = lstm ? g_out2 : g_out1;

    const int tid = threadIdx.x;

    // ---- stage weights once (rows j0..j0+31 of each gate + Wd) ----
    for (int idx = tid; idx < 5 * WJT * 64; idx += 256) {
        int g   = idx >> 11;
        int rem = idx & 2047;
        int lj  = rem >> 6;
        int k4  = (rem & 63) << 2;
        const float* src = (g < 4) ? (Wall + (size_t)(g * H_ + j0 + lj) * H_ + k4)
                                   : (Wd   + (size_t)(j0 + lj) * H_ + k4);
        *reinterpret_cast<float4*>(&wsm[((g << 5) + lj) * 256 + k4]) =
            *reinterpret_cast<const float4*>(src);
    }

    // ---- initial h/c: each CTA loads full 16x256 slab for its btile ----
    for (int idx = tid; idx < 16 * 64; idx += 256) {
        int r  = idx >> 6;
        int c4 = (idx & 63) << 2;
        *reinterpret_cast<float4*>(&hsm[r * HS_STRIDE + c4]) =
            *reinterpret_cast<const float4*>(&h0[(size_t)(b0 + r) * H_ + c4]);
        *reinterpret_cast<float4*>(&csm[r * HS_STRIDE + c4]) =
            *reinterpret_cast<const float4*>(&c0[(size_t)(b0 + r) * H_ + c4]);
    }
    __syncthreads();

    // thread -> (batch bi, adjacent j-pair jA=j0+2jj, jB=jA+1)
    const int bi = tid & 15;
    const int jj = tid >> 4;           // 0..15
    const int b  = b0 + bi;
    const int jA = j0 + 2 * jj;
    const int jB = jA + 1;
    const float wdbA = Wdb[jA];
    const float wdbB = Wdb[jB];

    const float* wA[5];
    const float* wB[5];
#pragma unroll
    for (int g = 0; g < 5; g++) {
        wA[g] = &wsm[((g << 5) + 2 * jj) * 256];
        wB[g] = &wsm[((g << 5) + 2 * jj + 1) * 256];
    }

    const uint32_t hAddr = smem_u32(&hsm[bi * HS_STRIDE + jA]);
    const uint32_t cAddr = smem_u32(&csm[bi * HS_STRIDE + jA]);
    const float* hrow = &hsm[bi * HS_STRIDE];
    const float* crow = &csm[bi * HS_STRIDE];

    for (int s = 0; s < SEQ_; s++) {
        // prefetch per-thread step inputs (jA even -> float2 aligned)
        const size_t row = (size_t)b * SEQ_ + s;
        const float t = tsp[row];
        const float* uxp = ux + row * G4H;
        float2 uxv[4];
#pragma unroll
        for (int g = 0; g < 4; g++)
            uxv[g] = *reinterpret_cast<const float2*>(uxp + g * H_ + jA);

        unsigned long long acc[10];
#pragma unroll
        for (int i = 0; i < 10; i++) acc[i] = 0ULL;

#pragma unroll 4
        for (int k = 0; k < H_; k += 4) {
            ulonglong2 h2 = *reinterpret_cast<const ulonglong2*>(&hrow[k]);
            ulonglong2 c2 = *reinterpret_cast<const ulonglong2*>(&crow[k]);
#pragma unroll
            for (int g = 0; g < 4; g++) {
                ulonglong2 w2 = *reinterpret_cast<const ulonglong2*>(&wA[g][k]);
                fma2(acc[g], h2.x, w2.x);
                fma2(acc[g], h2.y, w2.y);
                ulonglong2 v2 = *reinterpret_cast<const ulonglong2*>(&wB[g][k]);
                fma2(acc[5 + g], h2.x, v2.x);
                fma2(acc[5 + g], h2.y, v2.y);
            }
            ulonglong2 d2 = *reinterpret_cast<const ulonglong2*>(&wA[4][k]);
            fma2(acc[4], c2.x, d2.x);
            fma2(acc[4], c2.y, d2.y);
            ulonglong2 e2 = *reinterpret_cast<const ulonglong2*>(&wB[4][k]);
            fma2(acc[9], c2.x, e2.x);
            fma2(acc[9], c2.y, e2.y);
        }

        const float ccurA = crow[jA];
        const float ccurB = crow[jB];

        float hn[2], cn[2];
#pragma unroll
        for (int half = 0; half < 2; half++) {
            const int base = half * 5;
            float2 vf = unpack2(acc[base + 0]);
            float2 vi = unpack2(acc[base + 1]);
            float2 vo = unpack2(acc[base + 2]);
            float2 vc = unpack2(acc[base + 3]);
            float2 vd = unpack2(acc[base + 4]);
            const float af = vf.x + vf.y;
            const float ai = vi.x + vi.y;
            const float ao = vo.x + vo.y;
            const float ag = vc.x + vc.y;
            const float ad = vd.x + vd.y;
            const float wdb  = half ? wdbB : wdbA;
            const float ccur = half ? ccurB : ccurA;
            const float uf = half ? uxv[0].y : uxv[0].x;
            const float ui = half ? uxv[1].y : uxv[1].x;
            const float uo = half ? uxv[2].y : uxv[2].x;
            const float uc = half ? uxv[3].y : uxv[3].x;

            const float cs1  = tanhf(ad + wdb);
            const float cadj = ccur - cs1 + cs1 * t;
            const float gf = 1.f / (1.f + expf(-(af + uf)));
            const float gi = 1.f / (1.f + expf(-(ai + ui)));
            const float go = 1.f / (1.f + expf(-(ao + uo)));
            const float gc = 1.f / (1.f + expf(-(ag + uc)));
            cn[half] = gf * cadj + gi * gc;
            hn[half] = go * tanhf(cn[half]);
        }

        // emit h to the sequence output (global; no cross-step dependency)
        *reinterpret_cast<float2*>(outp + row * H_ + jA) = make_float2(hn[0], hn[1]);

        // ---- cluster barrier #1: everyone done READING hsm/csm ----
        CLUSTER_ARRIVE();
        CLUSTER_WAIT();

        // ---- broadcast my (jA,jB) slice of h,c to all 8 CTAs' smem ----
#pragma unroll
        for (int r = 0; r < 8; r++) {
            st_cluster_v2(mapa_u32(hAddr, (uint32_t)r), hn[0], hn[1]);
            st_cluster_v2(mapa_u32(cAddr, (uint32_t)r), cn[0], cn[1]);
        }

        // ---- cluster barrier #2: all writes visible before next read ----
        CLUSTER_ARRIVE();
        CLUSTER_WAIT();
    }
}

// ---------------- attention softmax ----------------
__global__ void attn_softmax_kernel(const float* __restrict__ wa)
{
    const int b    = blockIdx.x;
    const int tid  = threadIdx.x;
    const int lane = tid & 31;
    const int w    = tid >> 5;
    __shared__ float Es[SEQ_];
    __shared__ float mx, smv;

    for (int s = w; s < SEQ_; s += 8) {
        const float* o = g_out1 + ((size_t)b * SEQ_ + s) * H_;
        float sum = 0.f;
        for (int h = lane; h < H_; h += 32) sum += o[h] * wa[h];
#pragma unroll
        for (int off = 16; off; off >>= 1) sum += __shfl_xor_sync(0xffffffffu, sum, off);
        if (lane == 0) Es[s] = sum;
    }
    __syncthreads();
    if (tid == 0) {
        float m = -1e30f;
        for (int s = 0; s < SEQ_; s++) m = fmaxf(m, Es[s]);
        mx = m;
    }
    __syncthreads();
    if (tid < SEQ_) Es[tid] = expf(Es[tid] - mx);
    __syncthreads();
    if (tid == 0) {
        float t = 0.f;
        for (int s = 0; s < SEQ_; s++) t += Es[s];
        smv = t;
    }
    __syncthreads();
    if (tid < SEQ_) g_alpha[(size_t)b * SEQ_ + tid] = Es[tid] / smv;
}

// ---------------- ctx ----------------
__global__ void ctx_kernel()
{
    const int b = blockIdx.x;
    const int d = threadIdx.x;
    float acc = 0.f;
    for (int s = 0; s < SEQ_; s++) {
        size_t r = (size_t)b * SEQ_ + s;
        acc += g_embedded[r * D_ + d] * tanhf(g_beta[r * H_ + d]) * g_alpha[r];
    }
    g_ctx[(size_t)b * D_ + d] = acc;
}

// ---------------- output head ----------------
__global__ void out_kernel(const float* __restrict__ Wout, float* __restrict__ out)
{
    const int b = blockIdx.x;
    const int n = threadIdx.x;
    __shared__ float cx[D_];
    for (int d = threadIdx.x; d < D_; d += blockDim.x) cx[d] = g_ctx[(size_t)b * D_ + d];
    __syncthreads();
    float acc = 0.f;
    const float* wr = Wout + (size_t)n * H_;
#pragma unroll 8
    for (int d = 0; d < D_; d++) acc = fmaf(cx[d], wr[d], acc);
    out[(size_t)b * NCLS_ + n] = acc;
}

// ---------------- host launcher ----------------
extern "C" void kernel_launch(void* const* d_in, const int* in_sizes, int n_in,
                              void* d_out, int out_size)
{
    const float* inputs = (const float*)d_in[0];
    const float* tsp    = (const float*)d_in[1];
    const float* emb    = (const float*)d_in[2];
    const float* Wall1  = (const float*)d_in[3];
    const float* Wall1b = (const float*)d_in[4];
    const float* Uall1  = (const float*)d_in[5];
    const float* Uall1b = (const float*)d_in[6];
    const float* Wd1    = (const float*)d_in[7];
    const float* Wd1b   = (const float*)d_in[8];
    const float* Wall2  = (const float*)d_in[9];
    const float* Wall2b = (const float*)d_in[10];
    const float* Uall2  = (const float*)d_in[11];
    const float* Uall2b = (const float*)d_in[12];
    const float* Wd2    = (const float*)d_in[13];
    const float* Wd2b   = (const float*)d_in[14];
    const float* wa     = (const float*)d_in[15];
    const float* Wb     = (const float*)d_in[16];
    const float* Wout   = (const float*)d_in[17];
    const float* h01    = (const float*)d_in[18];
    const float* c01    = (const float*)d_in[19];
    const float* h02    = (const float*)d_in[20];
    const float* c02    = (const float*)d_in[21];
    float* out = (float*)d_out;

    void *p_emb, *p_ux1, *p_ux2, *p_out2, *p_beta;
    cudaGetSymbolAddress(&p_emb,  g_embedded);
    cudaGetSymbolAddress(&p_ux1,  g_ux1);
    cudaGetSymbolAddress(&p_ux2,  g_ux2);
    cudaGetSymbolAddress(&p_out2, g_out2);
    cudaGetSymbolAddress(&p_beta, g_beta);

    cudaFuncSetAttribute(lstm_scan_kernel,
                         cudaFuncAttributeMaxDynamicSharedMemorySize, SCAN_SMEM);

    const int M = B_ * SEQ_;   // 25600

    // 1) embedded = inputs @ emb
    gemm_kernel<false><<<dim3(D_ / GBN, M / GBM), 256>>>(
        inputs, emb, (float*)p_emb, M, D_, VOCAB_, nullptr, nullptr);

    // 2) ux = embedded @ Uall^T + (Uall_b + Wall_b)
    gemm_kernel<true><<<dim3(G4H / GBN, M / GBM), 256>>>(
        (const float*)p_emb, Uall1, (float*)p_ux1, M, G4H, D_, Uall1b, Wall1b);
    gemm_kernel<true><<<dim3(G4H / GBN, M / GBM), 256>>>(
        (const float*)p_emb, Uall2, (float*)p_ux2, M, G4H, D_, Uall2b, Wall2b);

    // 3) recurrent scan — 16 clusters x 8 CTAs, DSMEM h/c exchange
    lstm_scan_kernel<<<128, 256, SCAN_SMEM>>>(Wall1, Wd1, Wd1b, Wall2, Wd2, Wd2b, tsp,
                                              h01, c01, h02, c02);

    // 4) attention weights
    attn_softmax_kernel<<<B_, 256>>>(wa);

    // 5) beta = out2 @ Wb^T
    gemm_kernel<true><<<dim3(H_ / GBN, M / GBM), 256>>>(
        (const float*)p_out2, Wb, (float*)p_beta, M, H_, D_, nullptr, nullptr);

    // 6) context + output head
    ctx_kernel<<<B_, 256>>>();
    out_kernel<<<B_, 128>>>(Wout, out);
}

// round 8
// speedup vs baseline: 1.2482x; 1.2482x over previous
#include <cuda_runtime.h>
#include <math.h>
#include <stdint.h>

#define B_    128
#define SEQ_  200
#define VOCAB_ 1400
#define D_    256
#define H_    256
#define NCLS_ 128
#define G4H   1024

// ---------------- scratch (static __device__, no allocations) ----------------
__device__ float g_embedded[B_ * SEQ_ * D_];
__device__ float g_ux1[B_ * SEQ_ * G4H];
__device__ float g_ux2[B_ * SEQ_ * G4H];
__device__ float g_out1[B_ * SEQ_ * H_];
__device__ float g_out2[B_ * SEQ_ * H_];
__device__ float g_beta[B_ * SEQ_ * H_];
__device__ float g_hbuf[2 * 2 * B_ * H_];     // [lstm][parity][b][h]
__device__ float g_cbuf[2 * 2 * B_ * H_];
__device__ float g_alpha[B_ * SEQ_];
__device__ float g_ctx[B_ * D_];
__device__ unsigned g_cnt[16];                // monotonic per-group arrival counters

// ---------------- packed fp32 helpers (sm_103a f32x2 pipe) ----------------
__device__ __forceinline__ void fma2(unsigned long long& d, unsigned long long a, unsigned long long b) {
    asm("fma.rn.f32x2 %0, %1, %2, %0;" : "+l"(d) : "l"(a), "l"(b));
}
__device__ __forceinline__ unsigned long long dup2(float v) {
    unsigned long long r;
    asm("mov.b64 %0, {%1, %1};" : "=l"(r) : "f"(v));
    return r;
}
__device__ __forceinline__ float2 unpack2(unsigned long long v) {
    float2 f;
    asm("mov.b64 {%0, %1}, %2;" : "=f"(f.x), "=f"(f.y) : "l"(v));
    return f;
}

// ---------------- generic fp32 tiled GEMM (f32x2, pre-duplicated B) ----------------
// C[m][n] = sum_k A[m][k] * Bm (+ bias0[n] + bias1[n])
// BT=true : Bm is [N][K]   BT=false: Bm is [K][N]
#define GBM 128
#define GBN 64
#define GBK 16
#define BSTR 68     // Bs row stride in ulonglongs (544B = 16B multiple, 8-bank shift)

template <bool BT>
__global__ void gemm_kernel(const float* __restrict__ A, const float* __restrict__ Bm,
                            float* __restrict__ C, int M, int N, int K,
                            const float* __restrict__ bias0, const float* __restrict__ bias1)
{
    __shared__ float As[GBK][GBM + 4];
    __shared__ alignas(16) unsigned long long Bs[GBK][BSTR];

    const int tid   = threadIdx.x;       // 256 threads
    const int m_blk = blockIdx.y * GBM;
    const int n_blk = blockIdx.x * GBN;
    const int tx = tid & 15;
    const int ty = tid >> 4;
    const int m0 = ty * 8;
    const int n0 = tx * 4;

    unsigned long long acc2[4][4];       // m-pairs x n
#pragma unroll
    for (int i = 0; i < 4; i++)
#pragma unroll
        for (int j = 0; j < 4; j++) acc2[i][j] = 0ULL;

    const int a_row = tid >> 2;
    const int a_c4  = (tid & 3) * 4;

    for (int k0 = 0; k0 < K; k0 += GBK) {
#pragma unroll
        for (int r = 0; r < 2; r++) {
            int m = a_row + r * 64;
            float4 v = make_float4(0.f, 0.f, 0.f, 0.f);
            if (k0 + a_c4 < K)
                v = *reinterpret_cast<const float4*>(A + (size_t)(m_blk + m) * K + k0 + a_c4);
            As[a_c4 + 0][m] = v.x;
            As[a_c4 + 1][m] = v.y;
            As[a_c4 + 2][m] = v.z;
            As[a_c4 + 3][m] = v.w;
        }
        if (BT) {
            int n  = tid >> 2;           // 0..63
            int c4 = (tid & 3) * 4;
            float4 v = make_float4(0.f, 0.f, 0.f, 0.f);
            if (k0 + c4 < K)
                v = *reinterpret_cast<const float4*>(Bm + (size_t)(n_blk + n) * K + k0 + c4);
            Bs[c4 + 0][n] = dup2(v.x);
            Bs[c4 + 1][n] = dup2(v.y);
            Bs[c4 + 2][n] = dup2(v.z);
            Bs[c4 + 3][n] = dup2(v.w);
        } else {
            int kk = tid >> 4;           // 0..15
            int nn = (tid & 15) * 4;
            float4 v = make_float4(0.f, 0.f, 0.f, 0.f);
            if (k0 + kk < K)
                v = *reinterpret_cast<const float4*>(Bm + (size_t)(k0 + kk) * N + n_blk + nn);
            Bs[kk][nn + 0] = dup2(v.x);
            Bs[kk][nn + 1] = dup2(v.y);
            Bs[kk][nn + 2] = dup2(v.z);
            Bs[kk][nn + 3] = dup2(v.w);
        }
        __syncthreads();

#pragma unroll
        for (int kk = 0; kk < GBK; kk++) {
            const ulonglong2* ap = reinterpret_cast<const ulonglong2*>(&As[kk][m0]);
            ulonglong2 aA = ap[0];
            ulonglong2 aB = ap[1];
            const ulonglong2* bp = reinterpret_cast<const ulonglong2*>(&Bs[kk][n0]);
            ulonglong2 b01 = bp[0];
            ulonglong2 b23 = bp[1];
            unsigned long long bd[4] = {b01.x, b01.y, b23.x, b23.y};
            unsigned long long P[4] = {aA.x, aA.y, aB.x, aB.y};
#pragma unroll
            for (int p = 0; p < 4; p++)
#pragma unroll
                for (int j = 0; j < 4; j++) fma2(acc2[p][j], P[p], bd[j]);
        }
        __syncthreads();
    }

    float bv[4] = {0.f, 0.f, 0.f, 0.f};
    if (bias0) {
#pragma unroll
        for (int j = 0; j < 4; j++) bv[j] += bias0[n_blk + n0 + j];
    }
    if (bias1) {
#pragma unroll
        for (int j = 0; j < 4; j++) bv[j] += bias1[n_blk + n0 + j];
    }
#pragma unroll
    for (int p = 0; p < 4; p++) {
        float2 r0 = unpack2(acc2[p][0]);
        float2 r1 = unpack2(acc2[p][1]);
        float2 r2 = unpack2(acc2[p][2]);
        float2 r3 = unpack2(acc2[p][3]);
        float4 oA = make_float4(r0.x + bv[0], r1.x + bv[1], r2.x + bv[2], r3.x + bv[3]);
        float4 oB = make_float4(r0.y + bv[0], r1.y + bv[1], r2.y + bv[2], r3.y + bv[3]);
        *reinterpret_cast<float4*>(C + (size_t)(m_blk + m0 + 2 * p) * N + n_blk + n0)     = oA;
        *reinterpret_cast<float4*>(C + (size_t)(m_blk + m0 + 2 * p + 1) * N + n_blk + n0) = oB;
    }
}

// ---------------- init recurrent state + barrier counters ----------------
__global__ void init_state_kernel(const float* __restrict__ h01, const float* __restrict__ c01,
                                  const float* __restrict__ h02, const float* __restrict__ c02)
{
    int i = blockIdx.x * blockDim.x + threadIdx.x;
    if (i < 16) g_cnt[i] = 0;
    if (i >= B_ * H_) return;
    g_hbuf[(0 * 2 + 0) * B_ * H_ + i] = h01[i];
    g_cbuf[(0 * 2 + 0) * B_ * H_ + i] = c01[i];
    g_hbuf[(1 * 2 + 0) * B_ * H_ + i] = h02[i];
    g_cbuf[(1 * 2 + 0) * B_ * H_ + i] = c02[i];
}

// ---------------- persistent LSTM scan, occupancy-2 ----------------
// grid = 256 blocks: lstm(2) x btile(8, 16 batches) x jslice(16, 16 h-units).
// smem ~115KB -> 2 blocks/SM; co-resident blocks are from different sync groups,
// so barrier/restage latency of one is hidden under the other's fma2 stream.
#define SJT 16
#define HS2 260                     // h/c row stride: 1040B = 16B multiple (LDS.128 safe)
#define SCAN_SMEM ((5 * SJT * 256 + 2 * 16 * HS2) * 4)

__global__ __launch_bounds__(256) void lstm_scan_kernel(
    const float* __restrict__ Wall1, const float* __restrict__ Wd1, const float* __restrict__ Wdb1,
    const float* __restrict__ Wall2, const float* __restrict__ Wd2, const float* __restrict__ Wdb2,
    const float* __restrict__ tsp)
{
    extern __shared__ float sm[];
    float* wsm = sm;                           // [5][16][256]
    float* hsm = sm + 5 * SJT * 256;           // [16][260]
    float* csm = hsm + 16 * HS2;               // [16][260]

    const int bid   = blockIdx.x;
    const int lstm  = bid >> 7;
    const int btile = (bid >> 4) & 7;
    const int jt    = bid & 15;
    const int b0  = btile * 16;
    const int j0  = jt * SJT;
    const int grp = bid >> 4;                  // (lstm, btile): 16 groups of 16 blocks

    const float* Wall = lstm ? Wall2 : Wall1;
    const float* Wd   = lstm ? Wd2   : Wd1;
    const float* Wdb  = lstm ? Wdb2  : Wdb1;
    const float* ux   = lstm ? g_ux2 : g_ux1;
    float*       outp = lstm ? g_out2 : g_out1;

    const int tid = threadIdx.x;

    // ---- stage weights once: rows j0..j0+15 of f,i,o,cg gates + Wd ----
    for (int idx = tid; idx < 5 * SJT * 64; idx += 256) {
        int g   = idx >> 10;                   // /(16*64)
        int rem = idx & 1023;
        int lj  = rem >> 6;
        int k4  = (rem & 63) << 2;
        const float* src = (g < 4) ? (Wall + (size_t)(g * H_ + j0 + lj) * H_ + k4)
                                   : (Wd   + (size_t)(j0 + lj) * H_ + k4);
        *reinterpret_cast<float4*>(&wsm[((g << 4) + lj) * 256 + k4]) =
            *reinterpret_cast<const float4*>(src);
    }

    const int bi = tid & 15;
    const int jj = tid >> 4;                   // 0..15
    const int b  = b0 + bi;
    const int j  = j0 + jj;
    const float wdb = Wdb[j];

    const float* w[5];
#pragma unroll
    for (int g = 0; g < 5; g++) w[g] = &wsm[((g << 4) + jj) * 256];

    const float* hrow = &hsm[bi * HS2];
    const float* crow = &csm[bi * HS2];

    for (int s = 0; s < SEQ_; s++) {
        const int pr = s & 1;
        const float* hsrc = g_hbuf + (size_t)(lstm * 2 + pr) * B_ * H_;
        const float* csrc = g_cbuf + (size_t)(lstm * 2 + pr) * B_ * H_;
        for (int idx = tid; idx < 16 * 64; idx += 256) {
            int r  = idx >> 6;
            int c4 = (idx & 63) << 2;
            *reinterpret_cast<float4*>(&hsm[r * HS2 + c4]) =
                *reinterpret_cast<const float4*>(&hsrc[(size_t)(b0 + r) * H_ + c4]);
            *reinterpret_cast<float4*>(&csm[r * HS2 + c4]) =
                *reinterpret_cast<const float4*>(&csrc[(size_t)(b0 + r) * H_ + c4]);
        }
        __syncthreads();

        // per-thread step inputs (issue early; hidden under dot loop)
        const size_t row = (size_t)b * SEQ_ + s;
        const float t = tsp[row];
        const float* uxp = ux + row * G4H;
        const float uxf = uxp[0 * H_ + j];
        const float uxi = uxp[1 * H_ + j];
        const float uxo = uxp[2 * H_ + j];
        const float uxc = uxp[3 * H_ + j];

        unsigned long long acc[5];
#pragma unroll
        for (int i = 0; i < 5; i++) acc[i] = 0ULL;

#pragma unroll 4
        for (int k = 0; k < H_; k += 4) {
            ulonglong2 h2 = *reinterpret_cast<const ulonglong2*>(&hrow[k]);
            ulonglong2 c2 = *reinterpret_cast<const ulonglong2*>(&crow[k]);
#pragma unroll
            for (int g = 0; g < 4; g++) {
                ulonglong2 w2 = *reinterpret_cast<const ulonglong2*>(&w[g][k]);
                fma2(acc[g], h2.x, w2.x);
                fma2(acc[g], h2.y, w2.y);
            }
            ulonglong2 d2 = *reinterpret_cast<const ulonglong2*>(&w[4][k]);
            fma2(acc[4], c2.x, d2.x);
            fma2(acc[4], c2.y, d2.y);
        }

        float2 vf = unpack2(acc[0]);
        float2 vi = unpack2(acc[1]);
        float2 vo = unpack2(acc[2]);
        float2 vc = unpack2(acc[3]);
        float2 vd = unpack2(acc[4]);
        const float af = vf.x + vf.y;
        const float ai = vi.x + vi.y;
        const float ao = vo.x + vo.y;
        const float ag = vc.x + vc.y;
        const float ad = vd.x + vd.y;

        const float cs1  = tanhf(ad + wdb);
        const float ccur = crow[j];
        const float cadj = ccur - cs1 + cs1 * t;
        const float gf = 1.f / (1.f + expf(-(af + uxf)));
        const float gi = 1.f / (1.f + expf(-(ai + uxi)));
        const float go = 1.f / (1.f + expf(-(ao + uxo)));
        const float gc = 1.f / (1.f + expf(-(ag + uxc)));
        const float cnew = gf * cadj + gi * gc;
        const float hnew = go * tanhf(cnew);

        float* hdst = g_hbuf + (size_t)(lstm * 2 + (1 - pr)) * B_ * H_;
        float* cdst = g_cbuf + (size_t)(lstm * 2 + (1 - pr)) * B_ * H_;
        hdst[(size_t)b * H_ + j] = hnew;
        cdst[(size_t)b * H_ + j] = cnew;
        outp[row * H_ + j] = hnew;

        // ---- per-group barrier: release-add, acquire-poll (monotonic) ----
        if (s + 1 < SEQ_) {
            __syncthreads();
            if (tid == 0) {
                unsigned* cp = &g_cnt[grp];
                asm volatile("red.release.gpu.global.add.u32 [%0], 1;" :: "l"(cp) : "memory");
                const unsigned target = 16u * (unsigned)(s + 1);
                unsigned v;
                do {
                    asm volatile("ld.acquire.gpu.global.u32 %0, [%1];" : "=r"(v) : "l"(cp) : "memory");
                } while (v < target);
            }
            __syncthreads();
        }
    }
}

// ---------------- attention softmax ----------------
__global__ void attn_softmax_kernel(const float* __restrict__ wa)
{
    const int b    = blockIdx.x;
    const int tid  = threadIdx.x;
    const int lane = tid & 31;
    const int w    = tid >> 5;
    __shared__ float Es[SEQ_];
    __shared__ float mx, smv;

    for (int s = w; s < SEQ_; s += 8) {
        const float* o = g_out1 + ((size_t)b * SEQ_ + s) * H_;
        float sum = 0.f;
        for (int h = lane; h < H_; h += 32) sum += o[h] * wa[h];
#pragma unroll
        for (int off = 16; off; off >>= 1) sum += __shfl_xor_sync(0xffffffffu, sum, off);
        if (lane == 0) Es[s] = sum;
    }
    __syncthreads();
    if (tid == 0) {
        float m = -1e30f;
        for (int s = 0; s < SEQ_; s++) m = fmaxf(m, Es[s]);
        mx = m;
    }
    __syncthreads();
    if (tid < SEQ_) Es[tid] = expf(Es[tid] - mx);
    __syncthreads();
    if (tid == 0) {
        float t = 0.f;
        for (int s = 0; s < SEQ_; s++) t += Es[s];
        smv = t;
    }
    __syncthreads();
    if (tid < SEQ_) g_alpha[(size_t)b * SEQ_ + tid] = Es[tid] / smv;
}

// ---------------- ctx ----------------
__global__ void ctx_kernel()
{
    const int b = blockIdx.x;
    const int d = threadIdx.x;
    float acc = 0.f;
    for (int s = 0; s < SEQ_; s++) {
        size_t r = (size_t)b * SEQ_ + s;
        acc += g_embedded[r * D_ + d] * tanhf(g_beta[r * H_ + d]) * g_alpha[r];
    }
    g_ctx[(size_t)b * D_ + d] = acc;
}

// ---------------- output head ----------------
__global__ void out_kernel(const float* __restrict__ Wout, float* __restrict__ out)
{
    const int b = blockIdx.x;
    const int n = threadIdx.x;
    __shared__ float cx[D_];
    for (int d = threadIdx.x; d < D_; d += blockDim.x) cx[d] = g_ctx[(size_t)b * D_ + d];
    __syncthreads();
    float acc = 0.f;
    const float* wr = Wout + (size_t)n * H_;
#pragma unroll 8
    for (int d = 0; d < D_; d++) acc = fmaf(cx[d], wr[d], acc);
    out[(size_t)b * NCLS_ + n] = acc;
}

// ---------------- host launcher ----------------
extern "C" void kernel_launch(void* const* d_in, const int* in_sizes, int n_in,
                              void* d_out, int out_size)
{
    const float* inputs = (const float*)d_in[0];
    const float* tsp    = (const float*)d_in[1];
    const float* emb    = (const float*)d_in[2];
    const float* Wall1  = (const float*)d_in[3];
    const float* Wall1b = (const float*)d_in[4];
    const float* Uall1  = (const float*)d_in[5];
    const float* Uall1b = (const float*)d_in[6];
    const float* Wd1    = (const float*)d_in[7];
    const float* Wd1b   = (const float*)d_in[8];
    const float* Wall2  = (const float*)d_in[9];
    const float* Wall2b = (const float*)d_in[10];
    const float* Uall2  = (const float*)d_in[11];
    const float* Uall2b = (const float*)d_in[12];
    const float* Wd2    = (const float*)d_in[13];
    const float* Wd2b   = (const float*)d_in[14];
    const float* wa     = (const float*)d_in[15];
    const float* Wb     = (const float*)d_in[16];
    const float* Wout   = (const float*)d_in[17];
    const float* h01    = (const float*)d_in[18];
    const float* c01    = (const float*)d_in[19];
    const float* h02    = (const float*)d_in[20];
    const float* c02    = (const float*)d_in[21];
    float* out = (float*)d_out;

    void *p_emb, *p_ux1, *p_ux2, *p_out2, *p_beta;
    cudaGetSymbolAddress(&p_emb,  g_embedded);
    cudaGetSymbolAddress(&p_ux1,  g_ux1);
    cudaGetSymbolAddress(&p_ux2,  g_ux2);
    cudaGetSymbolAddress(&p_out2, g_out2);
    cudaGetSymbolAddress(&p_beta, g_beta);

    cudaFuncSetAttribute(lstm_scan_kernel,
                         cudaFuncAttributeMaxDynamicSharedMemorySize, SCAN_SMEM);

    const int M = B_ * SEQ_;   // 25600

    // 1) embedded = inputs @ emb
    gemm_kernel<false><<<dim3(D_ / GBN, M / GBM), 256>>>(
        inputs, emb, (float*)p_emb, M, D_, VOCAB_, nullptr, nullptr);

    // 2) ux = embedded @ Uall^T + (Uall_b + Wall_b)
    gemm_kernel<true><<<dim3(G4H / GBN, M / GBM), 256>>>(
        (const float*)p_emb, Uall1, (float*)p_ux1, M, G4H, D_, Uall1b, Wall1b);
    gemm_kernel<true><<<dim3(G4H / GBN, M / GBM), 256>>>(
        (const float*)p_emb, Uall2, (float*)p_ux2, M, G4H, D_, Uall2b, Wall2b);

    // 3) recurrent scan — 256 blocks, 2 per SM, release/acquire barrier
    init_state_kernel<<<(B_ * H_ + 255) / 256, 256>>>(h01, c01, h02, c02);
    lstm_scan_kernel<<<256, 256, SCAN_SMEM>>>(Wall1, Wd1, Wd1b, Wall2, Wd2, Wd2b, tsp);

    // 4) attention weights
    attn_softmax_kernel<<<B_, 256>>>(wa);

    // 5) beta = out2 @ Wb^T
    gemm_kernel<true><<<dim3(H_ / GBN, M / GBM), 256>>>(
        (const float*)p_out2, Wb, (float*)p_beta, M, H_, D_, nullptr, nullptr);

    // 6) context + output head
    ctx_kernel<<<B_, 256>>>();
    out_kernel<<<B_, 128>>>(Wout, out);
}